// round 9
// baseline (speedup 1.0000x reference)
#include <cuda_runtime.h>
#include <math.h>
#include <stdint.h>

#define Bq 256
#define Nq 256
#define Dq 512
#define Cq 1024
#define NCTA 128
#define NTHR 512

// Persistent scratch (device globals — no allocation allowed)
__device__ float g_txtn[Cq * Dq];      // normalized text (2 MB)
__device__ float g_pooled[Bq * Dq];    // pooled normalized tokens
__device__ float g_logits[Bq * Cq];    // final logits (pre-tau)
__device__ unsigned g_bar_count = 0;
__device__ volatile unsigned g_bar_gen = 0;

// Shared memory, reused across phases (32.2 KB max -> static OK)
union Smem {
    struct { float svec[16][Dq]; float sm[16]; float sden[16]; } p2;
    struct { uint32_t As[32][68]; uint32_t Bs[64][68]; } p3;
    float red[NTHR];
};

__device__ __forceinline__ void grid_bar() {
    __syncthreads();
    if (threadIdx.x == 0) {
        unsigned gen = g_bar_gen;
        __threadfence();
        if (atomicAdd(&g_bar_count, 1u) == NCTA - 1u) {
            g_bar_count = 0u;
            __threadfence();
            g_bar_gen = gen + 1u;          // release
        } else {
            while (g_bar_gen == gen) __nanosleep(64);
        }
        __threadfence();                   // acquire
    }
    __syncthreads();
}

__device__ __forceinline__ float warp_sum1(float v) {
#pragma unroll
    for (int o = 16; o; o >>= 1) v += __shfl_xor_sync(0xffffffffu, v, o);
    return v;
}

__device__ __forceinline__ void warp_sum4(float& a, float& b, float& c, float& d) {
#pragma unroll
    for (int o = 16; o; o >>= 1) {
        a += __shfl_xor_sync(0xffffffffu, a, o);
        b += __shfl_xor_sync(0xffffffffu, b, o);
        c += __shfl_xor_sync(0xffffffffu, c, o);
        d += __shfl_xor_sync(0xffffffffu, d, o);
    }
}

__device__ __forceinline__ uint32_t f2tf32(float v) {
    uint32_t r;
    asm("cvt.rna.tf32.f32 %0, %1;" : "=r"(r) : "f"(v));
    return r;
}
__device__ __forceinline__ uint4 tf32x4(float4 v) {
    return make_uint4(f2tf32(v.x), f2tf32(v.y), f2tf32(v.z), f2tf32(v.w));
}

__global__ void __launch_bounds__(NTHR, 1) k_mega(
    const float* __restrict__ toks,
    const float* __restrict__ txt,
    const float* __restrict__ p_log_tau,
    const float* __restrict__ p_log_attn_tau,
    const int* __restrict__ gt,
    float* __restrict__ out)
{
    __shared__ Smem S;
    int cta = blockIdx.x, tid = threadIdx.x;
    int w = tid >> 5, lane = tid & 31;

    // ======== Phase 1: normalize text rows (8 per CTA); zero out ========
    if (cta == 0 && tid == 0) out[0] = 0.f;
    if (w < 8) {
        int row = cta * 8 + w;
        const float4* src = (const float4*)(txt + (size_t)row * Dq);
        float4* dst = (float4*)(g_txtn + (size_t)row * Dq);
        float4 v[4];
        float ss = 0.f;
#pragma unroll
        for (int i = 0; i < 4; i++) {
            v[i] = src[lane + 32 * i];
            ss += v[i].x * v[i].x + v[i].y * v[i].y + v[i].z * v[i].z + v[i].w * v[i].w;
        }
        ss = warp_sum1(ss);
        float rn = 1.f / fmaxf(sqrtf(ss), 1e-12f);
#pragma unroll
        for (int i = 0; i < 4; i++) {
            float4 o;
            o.x = v[i].x * rn; o.y = v[i].y * rn; o.z = v[i].z * rn; o.w = v[i].w * rn;
            dst[lane + 32 * i] = o;
        }
    }
    grid_bar();

    // ======== Phase 2: fused online-softmax pooling (2 b's per CTA) ========
    {
        float at = expf(*p_log_attn_tau);
        at = fminf(fmaxf(at, 0.01f), 1.0f);
        float inv_at = 1.f / at;

#pragma unroll 1
        for (int bb = 0; bb < 2; bb++) {
            int b = cta * 2 + bb;
            int g = __ldg(&gt[b]);
            const float4* xrow = (const float4*)(g_txtn + (size_t)g * Dq);
            float4 xv[4];
#pragma unroll
            for (int i = 0; i < 4; i++) xv[i] = xrow[lane + 32 * i];

            // warp w handles rows [w*16, w*16+16) of this b, in 8 pairs
            const float4* base = (const float4*)(toks + ((size_t)b * Nq + w * 16) * Dq);

            float m = -1e30f, den = 0.f;
            float4 acc[4];
#pragma unroll
            for (int i = 0; i < 4; i++) acc[i] = make_float4(0.f, 0.f, 0.f, 0.f);

            float4 t0[4], t1[4], u0[4], u1[4];
#pragma unroll
            for (int i = 0; i < 4; i++) t0[i] = __ldcs(&base[lane + 32 * i]);
#pragma unroll
            for (int i = 0; i < 4; i++) t1[i] = __ldcs(&base[128 + lane + 32 * i]);

#pragma unroll
            for (int p = 0; p < 8; p++) {
                if (p < 7) {
                    const float4* nb = base + (size_t)(2 * p + 2) * 128;
#pragma unroll
                    for (int i = 0; i < 4; i++) u0[i] = __ldcs(&nb[lane + 32 * i]);
#pragma unroll
                    for (int i = 0; i < 4; i++) u1[i] = __ldcs(&nb[128 + lane + 32 * i]);
                }
                float ss0 = 0.f, dp0 = 0.f, ss1 = 0.f, dp1 = 0.f;
#pragma unroll
                for (int i = 0; i < 4; i++) {
                    ss0 += t0[i].x * t0[i].x + t0[i].y * t0[i].y + t0[i].z * t0[i].z + t0[i].w * t0[i].w;
                    dp0 += t0[i].x * xv[i].x + t0[i].y * xv[i].y + t0[i].z * xv[i].z + t0[i].w * xv[i].w;
                    ss1 += t1[i].x * t1[i].x + t1[i].y * t1[i].y + t1[i].z * t1[i].z + t1[i].w * t1[i].w;
                    dp1 += t1[i].x * xv[i].x + t1[i].y * xv[i].y + t1[i].z * xv[i].z + t1[i].w * xv[i].w;
                }
                warp_sum4(ss0, dp0, ss1, dp1);

                float rn0 = 1.f / fmaxf(sqrtf(ss0), 1e-12f);
                float rn1 = 1.f / fmaxf(sqrtf(ss1), 1e-12f);
                float s0 = dp0 * rn0 * inv_at;
                float s1 = dp1 * rn1 * inv_at;
                float mnew = fmaxf(m, fmaxf(s0, s1));
                float scale = expf(m - mnew);     // 0 on first pair
                float e0 = expf(s0 - mnew);
                float e1 = expf(s1 - mnew);
                den = den * scale + e0 + e1;
                float c0 = e0 * rn0, c1 = e1 * rn1;
#pragma unroll
                for (int i = 0; i < 4; i++) {
                    acc[i].x = fmaf(c1, t1[i].x, fmaf(c0, t0[i].x, acc[i].x * scale));
                    acc[i].y = fmaf(c1, t1[i].y, fmaf(c0, t0[i].y, acc[i].y * scale));
                    acc[i].z = fmaf(c1, t1[i].z, fmaf(c0, t0[i].z, acc[i].z * scale));
                    acc[i].w = fmaf(c1, t1[i].w, fmaf(c0, t0[i].w, acc[i].w * scale));
                }
                m = mnew;
                if (p < 7) {
#pragma unroll
                    for (int i = 0; i < 4; i++) { t0[i] = u0[i]; t1[i] = u1[i]; }
                }
            }

            // block combine: 16 warp-partials -> pooled[b,:]
            if (lane == 0) { S.p2.sm[w] = m; S.p2.sden[w] = den; }
            float4* sv = (float4*)S.p2.svec[w];
#pragma unroll
            for (int i = 0; i < 4; i++) sv[lane + 32 * i] = acc[i];
            __syncthreads();

            float M = S.p2.sm[0];
#pragma unroll
            for (int i = 1; i < 16; i++) M = fmaxf(M, S.p2.sm[i]);
            float denb = 0.f;
            float wsc[16];
#pragma unroll
            for (int i = 0; i < 16; i++) {
                wsc[i] = expf(S.p2.sm[i] - M);
                denb = fmaf(wsc[i], S.p2.sden[i], denb);
            }
            float v = 0.f;
#pragma unroll
            for (int i = 0; i < 16; i++) v = fmaf(wsc[i], S.p2.svec[i][tid], v);
            g_pooled[(size_t)b * Dq + tid] = v / denb;
            __syncthreads();   // protect svec before next bb reuses it
        }
    }
    grid_bar();

    // ======== Phase 3: logits = pooled @ txtn^T via TF32 MMA ========
    // 128 tiles of 32b x 64c, full K=512. Register-prefetch double buffer.
    {
        int b0 = (cta >> 4) * 32;     // 8 b-tiles
        int c0 = (cta & 15) * 64;     // 16 c-tiles
        int wm = w & 1, wn = w >> 1;  // 2 x 8 warp grid; each warp m16n8
        int qg = lane >> 2, qt = lane & 3;

        float d0 = 0.f, d1 = 0.f, d2 = 0.f, d3 = 0.f;

        int ar = tid >> 4, ac = (tid & 15) * 4;  // As: 32 rows x 64 k
        int br = tid >> 3, bc = (tid & 7) * 8;   // Bs: 64 rows x 64 k

        const float* pA = &g_pooled[(size_t)(b0 + ar) * Dq + ac];
        const float* pB = &g_txtn[(size_t)(c0 + br) * Dq + bc];

        float4 ra  = *(const float4*)pA;
        float4 rb0 = *(const float4*)pB;
        float4 rb1 = *(const float4*)(pB + 4);

#pragma unroll 1
        for (int ch = 0; ch < 8; ch++) {
            *(uint4*)&S.p3.As[ar][ac]     = tf32x4(ra);
            *(uint4*)&S.p3.Bs[br][bc]     = tf32x4(rb0);
            *(uint4*)&S.p3.Bs[br][bc + 4] = tf32x4(rb1);
            __syncthreads();
            if (ch < 7) {
                int kc = (ch + 1) * 64;
                ra  = *(const float4*)(pA + kc);
                rb0 = *(const float4*)(pB + kc);
                rb1 = *(const float4*)(pB + kc + 4);
            }
#pragma unroll
            for (int ks = 0; ks < 8; ks++) {
                int k = ks * 8;
                int row = wm * 16 + qg;
                uint32_t a0 = S.p3.As[row][k + qt];
                uint32_t a1 = S.p3.As[row + 8][k + qt];
                uint32_t a2 = S.p3.As[row][k + qt + 4];
                uint32_t a3 = S.p3.As[row + 8][k + qt + 4];
                int n = wn * 8 + qg;
                uint32_t bf0 = S.p3.Bs[n][k + qt];
                uint32_t bf1 = S.p3.Bs[n][k + qt + 4];
                asm volatile(
                    "mma.sync.aligned.m16n8k8.row.col.f32.tf32.tf32.f32 "
                    "{%0,%1,%2,%3}, {%4,%5,%6,%7}, {%8,%9}, {%0,%1,%2,%3};"
                    : "+f"(d0), "+f"(d1), "+f"(d2), "+f"(d3)
                    : "r"(a0), "r"(a1), "r"(a2), "r"(a3), "r"(bf0), "r"(bf1));
            }
            __syncthreads();
        }

        int row0 = b0 + wm * 16 + qg;
        int col = c0 + wn * 8 + 2 * qt;
        *(float2*)&g_logits[(size_t)row0 * Cq + col]       = make_float2(d0, d1);
        *(float2*)&g_logits[(size_t)(row0 + 8) * Cq + col] = make_float2(d2, d3);
    }
    grid_bar();

    // ======== Phase 4: cross entropy + mean (2 b's per CTA) ========
    {
        float tau = expf(*p_log_tau);
        tau = fminf(fmaxf(tau, 0.01f), 1.0f);
        float inv = 1.f / tau;

#pragma unroll 1
        for (int bb = 0; bb < 2; bb++) {
            int b = cta * 2 + bb;
            float l0 = g_logits[(size_t)b * Cq + tid] * inv;
            float l1 = g_logits[(size_t)b * Cq + tid + 512] * inv;

            S.red[tid] = fmaxf(l0, l1);
            __syncthreads();
#pragma unroll
            for (int s = 256; s; s >>= 1) {
                if (tid < s) S.red[tid] = fmaxf(S.red[tid], S.red[tid + s]);
                __syncthreads();
            }
            float mx = S.red[0];
            __syncthreads();

            S.red[tid] = expf(l0 - mx) + expf(l1 - mx);
            __syncthreads();
#pragma unroll
            for (int s = 256; s; s >>= 1) {
                if (tid < s) S.red[tid] += S.red[tid + s];
                __syncthreads();
            }
            if (tid == 0) {
                int g = gt[b];
                float xg = g_logits[(size_t)b * Cq + g] * inv;
                float nll = logf(S.red[0]) + mx - xg;
                atomicAdd(out, nll * (1.0f / (float)Bq));
            }
            __syncthreads();
        }
    }
}

// ---------------------------------------------------------------------------
extern "C" void kernel_launch(void* const* d_in, const int* in_sizes, int n_in,
                              void* d_out, int out_size) {
    const float* toks         = (const float*)d_in[0];  // [B,N,D] f32
    const float* txt          = (const float*)d_in[1];  // [C,D]   f32
    const float* log_tau      = (const float*)d_in[2];  // scalar
    const float* log_attn_tau = (const float*)d_in[3];  // scalar
    const int*   gt           = (const int*)d_in[4];    // [B] int32
    float* out = (float*)d_out;

    k_mega<<<NCTA, NTHR>>>(toks, txt, log_tau, log_attn_tau, gt, out);
}

// round 10
// speedup vs baseline: 1.0885x; 1.0885x over previous
#include <cuda_runtime.h>
#include <math.h>
#include <stdint.h>

#define Bq 256
#define Nq 256
#define Dq 512
#define Cq 1024
#define NCHUNK 8
#define CH_ROWS (Nq / NCHUNK)   // 32 rows per fused block
#define KSPLIT 16
#define KCH (Dq / KSPLIT)       // 32

// Scratch (device globals — no allocation allowed)
__device__ float  g_txtn[Cq * Dq];                 // normalized text (2 MB)
__device__ float  g_ppart[Bq * NCHUNK * Dq];       // partial weighted sums (4 MB)
__device__ float2 g_meta[Bq * NCHUNK];             // (m, den) per partial
__device__ float  g_pooled[Bq * Dq];               // pooled normalized tokens
__device__ float  g_lpart[KSPLIT * Bq * Cq];       // partial logits (16 MB)

__device__ __forceinline__ void warp_sum2(float& a, float& b) {
#pragma unroll
    for (int o = 16; o; o >>= 1) {
        a += __shfl_xor_sync(0xffffffffu, a, o);
        b += __shfl_xor_sync(0xffffffffu, b, o);
    }
}

__device__ __forceinline__ void warp_sum4(float& a, float& b, float& c, float& d) {
#pragma unroll
    for (int o = 16; o; o >>= 1) {
        a += __shfl_xor_sync(0xffffffffu, a, o);
        b += __shfl_xor_sync(0xffffffffu, b, o);
        c += __shfl_xor_sync(0xffffffffu, c, o);
        d += __shfl_xor_sync(0xffffffffu, d, o);
    }
}

__device__ __forceinline__ uint32_t f2tf32(float v) {
    uint32_t r;
    asm("cvt.rna.tf32.f32 %0, %1;" : "=r"(r) : "f"(v));
    return r;
}

// ---------------------------------------------------------------------------
// K1: L2-normalize text features; also zero the output scalar (for K5 atomic).
// One warp per row. grid = C/8, block = 256.
// ---------------------------------------------------------------------------
__global__ void k_txtnorm(const float* __restrict__ txt, float* __restrict__ out) {
    if (blockIdx.x == 0 && threadIdx.x == 0) out[0] = 0.f;
    int w = threadIdx.x >> 5, lane = threadIdx.x & 31;
    int row = blockIdx.x * 8 + w;
    const float4* src = (const float4*)(txt + (size_t)row * Dq);
    float4* dst = (float4*)(g_txtn + (size_t)row * Dq);
    float4 v[4];
    float ss = 0.f, dummy = 0.f;
#pragma unroll
    for (int i = 0; i < 4; i++) {
        v[i] = src[lane + 32 * i];
        ss += v[i].x * v[i].x + v[i].y * v[i].y + v[i].z * v[i].z + v[i].w * v[i].w;
    }
    warp_sum2(ss, dummy);
    float rn = 1.f / fmaxf(sqrtf(ss), 1e-12f);
#pragma unroll
    for (int i = 0; i < 4; i++) {
        float4 o;
        o.x = v[i].x * rn; o.y = v[i].y * rn; o.z = v[i].z * rn; o.w = v[i].w * rn;
        dst[lane + 32 * i] = o;
    }
}

// ---------------------------------------------------------------------------
// K2 (fused streaming pass): online softmax-weighted pooling, single read of
// toks (128 MB). Two row-pairs per warp with register prefetch (16 LDG.128
// in flight). grid = (NCHUNK, B) = 2048 blocks, block = 256 (8 warps x 4).
// ---------------------------------------------------------------------------
__global__ void k_fused(const float* __restrict__ toks,
                        const int* __restrict__ gt,
                        const float* __restrict__ p_log_attn_tau) {
    __shared__ float sm[8], sden[8];
    __shared__ float svec[8][Dq];

    int ch = blockIdx.x, b = blockIdx.y;
    int w = threadIdx.x >> 5, lane = threadIdx.x & 31;

    float at = expf(*p_log_attn_tau);
    at = fminf(fmaxf(at, 0.01f), 1.0f);
    float inv_at = 1.f / at;

    int g = __ldg(&gt[b]);
    const float4* xrow = (const float4*)(g_txtn + (size_t)g * Dq);
    float4 xv[4];
#pragma unroll
    for (int i = 0; i < 4; i++) xv[i] = xrow[lane + 32 * i];

    int row0 = b * Nq + ch * CH_ROWS + w * 4;
    const float4* base = (const float4*)(toks + (size_t)row0 * Dq);

    float m = -1e30f, den = 0.f;
    float4 acc[4];
#pragma unroll
    for (int i = 0; i < 4; i++) acc[i] = make_float4(0.f, 0.f, 0.f, 0.f);

    float4 t0[4], t1[4], u0[4], u1[4];
#pragma unroll
    for (int i = 0; i < 4; i++) t0[i] = __ldcs(&base[lane + 32 * i]);
#pragma unroll
    for (int i = 0; i < 4; i++) t1[i] = __ldcs(&base[128 + lane + 32 * i]);

#pragma unroll
    for (int rp = 0; rp < 2; rp++) {
        if (rp == 0) {
            // prefetch the second pair while the first reduces
#pragma unroll
            for (int i = 0; i < 4; i++) u0[i] = __ldcs(&base[256 + lane + 32 * i]);
#pragma unroll
            for (int i = 0; i < 4; i++) u1[i] = __ldcs(&base[384 + lane + 32 * i]);
        }
        float ss0 = 0.f, dp0 = 0.f, ss1 = 0.f, dp1 = 0.f;
#pragma unroll
        for (int i = 0; i < 4; i++) {
            ss0 += t0[i].x * t0[i].x + t0[i].y * t0[i].y + t0[i].z * t0[i].z + t0[i].w * t0[i].w;
            dp0 += t0[i].x * xv[i].x + t0[i].y * xv[i].y + t0[i].z * xv[i].z + t0[i].w * xv[i].w;
            ss1 += t1[i].x * t1[i].x + t1[i].y * t1[i].y + t1[i].z * t1[i].z + t1[i].w * t1[i].w;
            dp1 += t1[i].x * xv[i].x + t1[i].y * xv[i].y + t1[i].z * xv[i].z + t1[i].w * xv[i].w;
        }
        warp_sum4(ss0, dp0, ss1, dp1);

        float rn0 = 1.f / fmaxf(sqrtf(ss0), 1e-12f);
        float rn1 = 1.f / fmaxf(sqrtf(ss1), 1e-12f);
        float s0 = dp0 * rn0 * inv_at;
        float s1 = dp1 * rn1 * inv_at;
        float mnew = fmaxf(m, fmaxf(s0, s1));
        float scale = expf(m - mnew);
        float e0 = expf(s0 - mnew);
        float e1 = expf(s1 - mnew);
        den = den * scale + e0 + e1;
        float c0 = e0 * rn0, c1 = e1 * rn1;
#pragma unroll
        for (int i = 0; i < 4; i++) {
            acc[i].x = fmaf(c1, t1[i].x, fmaf(c0, t0[i].x, acc[i].x * scale));
            acc[i].y = fmaf(c1, t1[i].y, fmaf(c0, t0[i].y, acc[i].y * scale));
            acc[i].z = fmaf(c1, t1[i].z, fmaf(c0, t0[i].z, acc[i].z * scale));
            acc[i].w = fmaf(c1, t1[i].w, fmaf(c0, t0[i].w, acc[i].w * scale));
        }
        m = mnew;
        if (rp == 0) {
#pragma unroll
            for (int i = 0; i < 4; i++) { t0[i] = u0[i]; t1[i] = u1[i]; }
        }
    }

    if (lane == 0) { sm[w] = m; sden[w] = den; }
    float4* sv = (float4*)svec[w];
#pragma unroll
    for (int i = 0; i < 4; i++) sv[lane + 32 * i] = acc[i];
    __syncthreads();

    float M = sm[0];
#pragma unroll
    for (int i = 1; i < 8; i++) M = fmaxf(M, sm[i]);
    float wsc[8];
    float denb = 0.f;
#pragma unroll
    for (int i = 0; i < 8; i++) { wsc[i] = expf(sm[i] - M); denb = fmaf(wsc[i], sden[i], denb); }

    int tid = threadIdx.x;
    float* outp = g_ppart + (size_t)(b * NCHUNK + ch) * Dq;
#pragma unroll
    for (int rep = 0; rep < 2; rep++) {
        int d = tid + rep * 256;
        float v = 0.f;
#pragma unroll
        for (int i = 0; i < 8; i++) v = fmaf(wsc[i], svec[i][d], v);
        outp[d] = v;
    }
    if (tid == 0) g_meta[b * NCHUNK + ch] = make_float2(M, denb);
}

// ---------------------------------------------------------------------------
// K3: combine NCHUNK partials per b -> pooled[b,:]. grid = B, block = 128.
// ---------------------------------------------------------------------------
__global__ void k_combine() {
    int b = blockIdx.x, tid = threadIdx.x;
    float2 mt[NCHUNK];
#pragma unroll
    for (int i = 0; i < NCHUNK; i++) mt[i] = g_meta[b * NCHUNK + i];
    float M = mt[0].x;
#pragma unroll
    for (int i = 1; i < NCHUNK; i++) M = fmaxf(M, mt[i].x);
    float den = 0.f;
    float sc[NCHUNK];
#pragma unroll
    for (int i = 0; i < NCHUNK; i++) { sc[i] = expf(mt[i].x - M); den = fmaf(sc[i], mt[i].y, den); }
    float inv_den = 1.f / den;

    const float4* part = (const float4*)(g_ppart + (size_t)b * NCHUNK * Dq);
    float4 acc = make_float4(0.f, 0.f, 0.f, 0.f);
#pragma unroll
    for (int i = 0; i < NCHUNK; i++) {
        float4 p = part[(size_t)i * (Dq / 4) + tid];
        acc.x = fmaf(sc[i], p.x, acc.x);
        acc.y = fmaf(sc[i], p.y, acc.y);
        acc.z = fmaf(sc[i], p.z, acc.z);
        acc.w = fmaf(sc[i], p.w, acc.w);
    }
    acc.x *= inv_den; acc.y *= inv_den; acc.z *= inv_den; acc.w *= inv_den;
    ((float4*)(g_pooled + (size_t)b * Dq))[tid] = acc;
}

// ---------------------------------------------------------------------------
// K4: partial logits via TF32 mma.sync (m16n8k8, fp32 accumulate).
// CTA = 256 thr = 8 warps (2 M-warps x 4 N-warps), tile 64 x 128, KCH = 32.
// grid = (C/128, B/64, KSPLIT) = (8, 4, 16) = 512 CTAs.
// ---------------------------------------------------------------------------
__global__ void __launch_bounds__(256) k_gemm() {
    __shared__ __align__(16) uint32_t As[64][36];    // [m][k] tf32
    __shared__ __align__(16) uint32_t Bs[128][36];   // [n][k] tf32

    int tid = threadIdx.x;
    int c0 = blockIdx.x * 128;
    int b0 = blockIdx.y * 64;
    int kbase = blockIdx.z * KCH;

    int warp = tid >> 5, lane = tid & 31;
    int warpM = warp & 1;          // 0..1  -> 32 rows each
    int warpN = warp >> 1;         // 0..3  -> 32 cols each
    int qg = lane >> 2;            // quad group 0..7
    int qt = lane & 3;             // thread in quad 0..3

    // ---- load + tf32-convert tiles (KCH=32 cols) ----
    {
        int r = tid >> 3;          // 0..31
        int cc = (tid & 7) * 4;    // 0..28
#pragma unroll
        for (int i = 0; i < 2; i++) {   // As: 64 rows
            int row = r + 32 * i;
            float4 v = *(const float4*)&g_pooled[(size_t)(b0 + row) * Dq + kbase + cc];
            uint4 u = make_uint4(f2tf32(v.x), f2tf32(v.y), f2tf32(v.z), f2tf32(v.w));
            *(uint4*)&As[row][cc] = u;
        }
#pragma unroll
        for (int i = 0; i < 4; i++) {   // Bs: 128 rows
            int row = r + 32 * i;
            float4 v = *(const float4*)&g_txtn[(size_t)(c0 + row) * Dq + kbase + cc];
            uint4 u = make_uint4(f2tf32(v.x), f2tf32(v.y), f2tf32(v.z), f2tf32(v.w));
            *(uint4*)&Bs[row][cc] = u;
        }
    }
    __syncthreads();

    float d[2][4][4];   // [mtile][ntile][frag]
#pragma unroll
    for (int mt = 0; mt < 2; mt++)
#pragma unroll
        for (int nt = 0; nt < 4; nt++)
#pragma unroll
            for (int f = 0; f < 4; f++) d[mt][nt][f] = 0.f;

#pragma unroll
    for (int ks = 0; ks < KCH / 8; ks++) {
        int k = ks * 8;
        uint32_t a[2][4];
#pragma unroll
        for (int mt = 0; mt < 2; mt++) {
            int row = warpM * 32 + mt * 16 + qg;
            a[mt][0] = As[row][k + qt];
            a[mt][1] = As[row + 8][k + qt];
            a[mt][2] = As[row][k + qt + 4];
            a[mt][3] = As[row + 8][k + qt + 4];
        }
        uint32_t bf[4][2];
#pragma unroll
        for (int nt = 0; nt < 4; nt++) {
            int n = warpN * 32 + nt * 8 + qg;
            bf[nt][0] = Bs[n][k + qt];
            bf[nt][1] = Bs[n][k + qt + 4];
        }
#pragma unroll
        for (int mt = 0; mt < 2; mt++)
#pragma unroll
            for (int nt = 0; nt < 4; nt++) {
                asm volatile(
                    "mma.sync.aligned.m16n8k8.row.col.f32.tf32.tf32.f32 "
                    "{%0,%1,%2,%3}, {%4,%5,%6,%7}, {%8,%9}, {%0,%1,%2,%3};"
                    : "+f"(d[mt][nt][0]), "+f"(d[mt][nt][1]),
                      "+f"(d[mt][nt][2]), "+f"(d[mt][nt][3])
                    : "r"(a[mt][0]), "r"(a[mt][1]), "r"(a[mt][2]), "r"(a[mt][3]),
                      "r"(bf[nt][0]), "r"(bf[nt][1]));
            }
    }

    // ---- epilogue: float2 stores ----
    float* dst = g_lpart + ((size_t)blockIdx.z * Bq) * Cq;
#pragma unroll
    for (int mt = 0; mt < 2; mt++) {
        int row0 = b0 + warpM * 32 + mt * 16 + qg;
#pragma unroll
        for (int nt = 0; nt < 4; nt++) {
            int col = c0 + warpN * 32 + nt * 8 + 2 * qt;
            *(float2*)&dst[(size_t)row0 * Cq + col] =
                make_float2(d[mt][nt][0], d[mt][nt][1]);
            *(float2*)&dst[(size_t)(row0 + 8) * Cq + col] =
                make_float2(d[mt][nt][2], d[mt][nt][3]);
        }
    }
}

// ---------------------------------------------------------------------------
// K5: cross entropy (summing KSPLIT logit partials) + mean via atomicAdd.
// grid = B, block = 256.
// ---------------------------------------------------------------------------
__global__ void k_ce(const float* __restrict__ p_log_tau,
                     const int* __restrict__ gt,
                     float* __restrict__ out) {
    __shared__ float red[256];
    int b = blockIdx.x, tid = threadIdx.x;
    float tau = expf(*p_log_tau);
    tau = fminf(fmaxf(tau, 0.01f), 1.0f);
    float inv = 1.f / tau;

    float l[4];
    float mx = -1e30f;
#pragma unroll
    for (int i = 0; i < 4; i++) {
        int idx = tid + i * 256;
        float v = 0.f;
#pragma unroll
        for (int ks = 0; ks < KSPLIT; ks++)
            v += g_lpart[((size_t)ks * Bq + b) * Cq + idx];
        l[i] = v * inv;
        mx = fmaxf(mx, l[i]);
    }
    red[tid] = mx;
    __syncthreads();
#pragma unroll
    for (int s = 128; s; s >>= 1) {
        if (tid < s) red[tid] = fmaxf(red[tid], red[tid + s]);
        __syncthreads();
    }
    mx = red[0];
    __syncthreads();

    float sum = 0.f;
#pragma unroll
    for (int i = 0; i < 4; i++) sum += expf(l[i] - mx);
    red[tid] = sum;
    __syncthreads();
#pragma unroll
    for (int s = 128; s; s >>= 1) {
        if (tid < s) red[tid] += red[tid + s];
        __syncthreads();
    }
    if (tid == 0) {
        int g = gt[b];
        float xg = 0.f;
#pragma unroll
        for (int ks = 0; ks < KSPLIT; ks++)
            xg += g_lpart[((size_t)ks * Bq + b) * Cq + g];
        xg *= inv;
        float nll = logf(red[0]) + mx - xg;
        atomicAdd(out, nll * (1.0f / (float)Bq));
    }
}

// ---------------------------------------------------------------------------
extern "C" void kernel_launch(void* const* d_in, const int* in_sizes, int n_in,
                              void* d_out, int out_size) {
    const float* toks         = (const float*)d_in[0];  // [B,N,D] f32
    const float* txt          = (const float*)d_in[1];  // [C,D]   f32
    const float* log_tau      = (const float*)d_in[2];  // scalar
    const float* log_attn_tau = (const float*)d_in[3];  // scalar
    const int*   gt           = (const int*)d_in[4];    // [B] int32
    float* out = (float*)d_out;

    k_txtnorm<<<Cq / 8, 256>>>(txt, out);
    dim3 gf(NCHUNK, Bq);
    k_fused<<<gf, 256>>>(toks, gt, log_attn_tau);
    k_combine<<<Bq, 128>>>();
    dim3 gg(Cq / 128, Bq / 64, KSPLIT);
    k_gemm<<<gg, 256>>>();
    k_ce<<<Bq, 256>>>(log_tau, gt, out);
}